// round 5
// baseline (speedup 1.0000x reference)
#include <cuda_runtime.h>

#define NTOK 16384
#define NEXP 64
#define DIM  2048
#define KC   32
#define KPAIRS (KC / 2)        // 16
#define CHUNKS (DIM / KC)      // 64
#define TOKB 64
#define THREADS 256
#define XROWF 36               // floats per X token row (32 + 4 pad) = 144B
#define XROWU (XROWF / 2)      // 18 ull
#define NBUF 4

typedef unsigned long long ull;

// W packed as f32x2-per-kpair ull: u = kp*64 + p*8 + sub holds {W[8*sub+p][2kp], W[8*sub+p][2kp+1]}
// => warp-wide LDS.64 at fixed p = 8 subs x 8B contiguous 64B, 4-lane broadcast: 1 wavefront.
__device__ ull g_Wp[(DIM / 2) * 64];

// ---------- f32x2 helpers ----------
__device__ __forceinline__ void unpack2(ull v, float& lo, float& hi) {
    asm("mov.b64 {%0, %1}, %2;" : "=f"(lo), "=f"(hi) : "l"(v));
}
__device__ __forceinline__ ull fma2(ull a, ull b, ull c) {
    ull d;
    asm("fma.rn.f32x2 %0, %1, %2, %3;" : "=l"(d) : "l"(a), "l"(b), "l"(c));
    return d;
}
__device__ __forceinline__ void cpasync16(unsigned s, const void* g) {
    asm volatile("cp.async.cg.shared.global [%0], [%1], 16;" :: "r"(s), "l"(g));
}
__device__ __forceinline__ void cp_commit() {
    asm volatile("cp.async.commit_group;");
}

// ---------- kernel 1: pack + permute W ----------
__global__ void prep_W(const float* __restrict__ W) {
    int i = blockIdx.x * blockDim.x + threadIdx.x;
    if (i < DIM * NEXP) {
        int e = i >> 11;            // expert row (k contiguous -> coalesced read)
        int k = i & (DIM - 1);
        int kp = k >> 1, w = k & 1;
        int sub = e >> 3, p = e & 7;
        ((float*)g_Wp)[(kp * 64 + p * 8 + sub) * 2 + w] = W[i];
    }
}

// ---------- kernel 2: fused GEMM + bias + top-2 + softmax ----------
__global__ __launch_bounds__(THREADS)
void gate_kernel(const float* __restrict__ inp,
                 const float* __restrict__ bias,
                 float* __restrict__ out,
                 int out_size) {
    __shared__ __align__(16) ull   Wsm[NBUF][KPAIRS * 64];    // 4 x 8 KB
    __shared__ __align__(16) float Xsm[NBUF][TOKB * XROWF];   // 4 x 9 KB

    const int tid = threadIdx.x;
    const int sub = tid & 7;          // expert group: experts 8*sub .. 8*sub+7
    const int tp  = tid >> 3;         // 0..31; tokens tp, tp+32
    const int tokBase = blockIdx.x * TOKB;

    // staging geometry: W 32B/thread contiguous; X token=tid>>2, quarter=(tid&3)*32B
    const int xTok  = tid >> 2;
    const int xPart = tid & 3;
    const float* xSrcBase = inp + (size_t)(tokBase + xTok) * DIM + xPart * 8;

    ull acc[2][8];
#pragma unroll
    for (int j = 0; j < 2; j++)
#pragma unroll
        for (int p = 0; p < 8; p++) acc[j][p] = 0ull;

    const unsigned wD0 = (unsigned)__cvta_generic_to_shared(&Wsm[0][0]);
    const unsigned xD0 = (unsigned)__cvta_generic_to_shared(&Xsm[0][0]);
    const unsigned wBufSz = KPAIRS * 64 * 8;   // 8192 B
    const unsigned xBufSz = TOKB * XROWF * 4;  // 9216 B

    auto stage = [&](int c, int b) {
        unsigned wd = wD0 + b * wBufSz + tid * 32;
        const char* ws = (const char*)(g_Wp + (size_t)c * KPAIRS * 64) + tid * 32;
        cpasync16(wd, ws);
        cpasync16(wd + 16, ws + 16);
        unsigned xd = xD0 + b * xBufSz + (xTok * XROWF + xPart * 8) * 4;
        const float* xs = xSrcBase + c * KC;
        cpasync16(xd, xs);
        cpasync16(xd + 16, xs + 4);
    };

    // prologue: chunks 0 and 1 in flight
    stage(0, 0); cp_commit();
    stage(1, 1); cp_commit();

    for (int c = 0; c < CHUNKS; c++) {
        const int b = c & (NBUF - 1);
        if (c + 2 < CHUNKS) stage(c + 2, (c + 2) & (NBUF - 1));
        cp_commit();                                // (possibly empty group)
        asm volatile("cp.async.wait_group 2;");     // chunk c's group complete
        __syncthreads();                            // single barrier per chunk (NBUF=4 => WAR safe)

        const ull* wb = &Wsm[b][sub];
        const ull* x0p = (const ull*)&Xsm[b][0] + (size_t)tp * XROWU;
        const ull* x1p = x0p + 32 * XROWU;
#pragma unroll
        for (int kp = 0; kp < KPAIRS; kp++) {
            ull w0 = wb[kp * 64 + 0];
            ull w1 = wb[kp * 64 + 8];
            ull w2 = wb[kp * 64 + 16];
            ull w3 = wb[kp * 64 + 24];
            ull w4 = wb[kp * 64 + 32];
            ull w5 = wb[kp * 64 + 40];
            ull w6 = wb[kp * 64 + 48];
            ull w7 = wb[kp * 64 + 56];
            ull x0 = x0p[kp];
            ull x1 = x1p[kp];
            acc[0][0] = fma2(w0, x0, acc[0][0]);
            acc[0][1] = fma2(w1, x0, acc[0][1]);
            acc[0][2] = fma2(w2, x0, acc[0][2]);
            acc[0][3] = fma2(w3, x0, acc[0][3]);
            acc[0][4] = fma2(w4, x0, acc[0][4]);
            acc[0][5] = fma2(w5, x0, acc[0][5]);
            acc[0][6] = fma2(w6, x0, acc[0][6]);
            acc[0][7] = fma2(w7, x0, acc[0][7]);
            acc[1][0] = fma2(w0, x1, acc[1][0]);
            acc[1][1] = fma2(w1, x1, acc[1][1]);
            acc[1][2] = fma2(w2, x1, acc[1][2]);
            acc[1][3] = fma2(w3, x1, acc[1][3]);
            acc[1][4] = fma2(w4, x1, acc[1][4]);
            acc[1][5] = fma2(w5, x1, acc[1][5]);
            acc[1][6] = fma2(w6, x1, acc[1][6]);
            acc[1][7] = fma2(w7, x1, acc[1][7]);
        }
        // no trailing barrier: with NBUF=4 and per-chunk barrier above,
        // stage(c+2) can only race compute(c-1): buffers (c+2)%4 != (c-1)%4.
    }

    // ---- fused epilogue: reduce pair halves, +bias, top-2, softmax ----
    const int half = out_size >> 1;
    const int e0 = sub * 8;
    float bv[8];
#pragma unroll
    for (int p = 0; p < 8; p++) bv[p] = bias[e0 + p];

#pragma unroll
    for (int j = 0; j < 2; j++) {
        float v0 = -3.4e38f, v1 = -3.4e38f;
        int   i0 = -1,       i1 = -1;
#pragma unroll
        for (int p = 0; p < 8; p++) {
            float lo, hi;
            unpack2(acc[j][p], lo, hi);
            float f = lo + hi + bv[p];
            int e = e0 + p;
            if (f > v0)      { v1 = v0; i1 = i0; v0 = f; i0 = e; }
            else if (f > v1) { v1 = f;  i1 = e; }
        }
        // butterfly merge over the 8 sub-lanes owning this token
#pragma unroll
        for (int ofs = 1; ofs < 8; ofs <<= 1) {
            float u0 = __shfl_xor_sync(0xFFFFFFFFu, v0, ofs);
            float u1 = __shfl_xor_sync(0xFFFFFFFFu, v1, ofs);
            int   j0 = __shfl_xor_sync(0xFFFFFFFFu, i0, ofs);
            int   j1 = __shfl_xor_sync(0xFFFFFFFFu, i1, ofs);
            bool afirst = (v0 > u0) || (v0 == u0 && i0 < j0);
            float nv0, nv1; int ni0, ni1;
            if (afirst) {
                nv0 = v0; ni0 = i0;
                bool s = (u0 > v1) || (u0 == v1 && j0 < i1);
                nv1 = s ? u0 : v1; ni1 = s ? j0 : i1;
            } else {
                nv0 = u0; ni0 = j0;
                bool s = (v0 > u1) || (v0 == u1 && i0 < j1);
                nv1 = s ? v0 : u1; ni1 = s ? i0 : j1;
            }
            v0 = nv0; v1 = nv1; i0 = ni0; i1 = ni1;
        }
        if (sub == 0) {
            int tok = tokBase + tp + 32 * j;
            float e  = expf(v1 - v0);
            float s0 = 1.0f / (1.0f + e);
            float s1 = e * s0;
            out[tok * 2 + 0] = (float)i0;
            out[tok * 2 + 1] = (float)i1;
            out[half + tok * 2 + 0] = s0;
            out[half + tok * 2 + 1] = s1;
        }
    }
}

extern "C" void kernel_launch(void* const* d_in, const int* in_sizes, int n_in,
                              void* d_out, int out_size) {
    const float* inp  = (const float*)d_in[0];   // [16384, 2048]
    const float* W    = (const float*)d_in[1];   // [64, 2048]
    const float* bias = (const float*)d_in[2];   // [64]
    float* out = (float*)d_out;

    prep_W<<<(DIM * NEXP + 255) / 256, 256>>>(W);
    gate_kernel<<<NTOK / TOKB, THREADS>>>(inp, bias, out, out_size);
}

// round 7
// speedup vs baseline: 1.2522x; 1.2522x over previous
#include <cuda_runtime.h>

#define NTOK 16384
#define NEXP 64
#define DIM  2048
#define KC   32
#define KPAIRS (KC / 2)        // 16
#define HCHUNKS 32             // chunks per K-half (1024/32)
#define TOKB 64
#define THREADS 256
#define XROWF 36               // floats per X token row (32 + 4 pad) = 144B
#define XROWU (XROWF / 2)      // 18 ull
#define NBUF 3
#define REDROW 36              // reduction scratch row stride (floats): 144B, 16B-aligned

typedef unsigned long long ull;

// W packed as f32x2-per-kpair ull: u = kp*64 + p*8 + sub holds {W[8*sub+p][2kp], W[8*sub+p][2kp+1]}
// => warp-wide LDS.64 at fixed p = 8 subs x 8B contiguous 64B, 4-lane broadcast: 1 wavefront.
__device__ ull g_Wp[(DIM / 2) * 64];

// ---------- f32x2 helpers ----------
__device__ __forceinline__ void unpack2(ull v, float& lo, float& hi) {
    asm("mov.b64 {%0, %1}, %2;" : "=f"(lo), "=f"(hi) : "l"(v));
}
__device__ __forceinline__ ull fma2(ull a, ull b, ull c) {
    ull d;
    asm("fma.rn.f32x2 %0, %1, %2, %3;" : "=l"(d) : "l"(a), "l"(b), "l"(c));
    return d;
}
__device__ __forceinline__ void cpasync16(unsigned s, const void* g) {
    asm volatile("cp.async.cg.shared.global [%0], [%1], 16;" :: "r"(s), "l"(g));
}
__device__ __forceinline__ void cp_commit() {
    asm volatile("cp.async.commit_group;");
}

// ---------- kernel 1: pack + permute W ----------
__global__ void prep_W(const float* __restrict__ W) {
    int i = blockIdx.x * blockDim.x + threadIdx.x;
    if (i < DIM * NEXP) {
        int e = i >> 11;            // expert row (k contiguous -> coalesced read)
        int k = i & (DIM - 1);
        int kp = k >> 1, w = k & 1;
        int sub = e >> 3, p = e & 7;
        ((float*)g_Wp)[(kp * 64 + p * 8 + sub) * 2 + w] = W[i];
    }
}

// ---------- kernel 2: fused GEMM (intra-block split-K) + bias + top-2 + softmax ----------
__global__ __launch_bounds__(THREADS, 2)
void gate_kernel(const float* __restrict__ inp,
                 const float* __restrict__ bias,
                 float* __restrict__ out,
                 int out_size) {
    // per K-crew staging: W 3x8KB + X 3x9KB = 51KB; two crews = 102KB
    __shared__ __align__(16) ull   Wsm[2][NBUF][KPAIRS * 64];
    __shared__ __align__(16) float Xsm[2][NBUF][TOKB * XROWF];

    const int tid  = threadIdx.x;
    const int ks   = tid >> 7;        // K-crew: 0 or 1
    const int t128 = tid & 127;
    const int sub  = t128 & 7;        // expert group: experts 8*sub .. 8*sub+7
    const int tp   = t128 >> 3;       // 0..15; tokens tp, tp+16, tp+32, tp+48
    const int tokBase = blockIdx.x * TOKB;
    const int kOff = ks * (DIM / 2);  // this crew's K offset (floats)

    // staging geometry (within crew): W 64B/thread; X token=t128>>1, half=(t128&1)*64B
    const int xTok  = t128 >> 1;
    const int xHalf = t128 & 1;
    const float* xSrcBase = inp + (size_t)(tokBase + xTok) * DIM + kOff + xHalf * 16;
    const ull* wSrcBase = g_Wp + (size_t)(kOff / 2) * 64;   // crew's first kpair row

    ull acc[4][8];
#pragma unroll
    for (int j = 0; j < 4; j++)
#pragma unroll
        for (int p = 0; p < 8; p++) acc[j][p] = 0ull;

    const unsigned wD0 = (unsigned)__cvta_generic_to_shared(&Wsm[ks][0][0]);
    const unsigned xD0 = (unsigned)__cvta_generic_to_shared(&Xsm[ks][0][0]);
    const unsigned wBufSz = KPAIRS * 64 * 8;   // 8192 B
    const unsigned xBufSz = TOKB * XROWF * 4;  // 9216 B

    auto stage = [&](int c, int b) {
        unsigned wd = wD0 + b * wBufSz + t128 * 64;
        const char* ws = (const char*)(wSrcBase + (size_t)c * KPAIRS * 64) + t128 * 64;
#pragma unroll
        for (int i = 0; i < 4; i++) cpasync16(wd + i * 16, ws + i * 16);
        unsigned xd = xD0 + b * xBufSz + (xTok * XROWF + xHalf * 16) * 4;
        const float* xs = xSrcBase + c * KC;
#pragma unroll
        for (int i = 0; i < 4; i++) cpasync16(xd + i * 16, xs + i * 4);
    };

    stage(0, 0);
    cp_commit();

    for (int c = 0; c < HCHUNKS; c++) {
        const int b = c % NBUF;
        if (c + 1 < HCHUNKS) {
            stage(c + 1, (c + 1) % NBUF);
            cp_commit();
            asm volatile("cp.async.wait_group 1;");   // chunk c complete
        } else {
            cp_commit();
            asm volatile("cp.async.wait_group 0;");
        }
        __syncthreads();  // single barrier: NBUF=3, distance-1 => stage(c+1) vs compute(c-1) disjoint

        const ull* wb = &Wsm[ks][b][sub];
        const ull* x0p = (const ull*)&Xsm[ks][b][0] + (size_t)tp * XROWU;
#pragma unroll
        for (int kp = 0; kp < KPAIRS; kp++) {
            ull w0 = wb[kp * 64 + 0];
            ull w1 = wb[kp * 64 + 8];
            ull w2 = wb[kp * 64 + 16];
            ull w3 = wb[kp * 64 + 24];
            ull w4 = wb[kp * 64 + 32];
            ull w5 = wb[kp * 64 + 40];
            ull w6 = wb[kp * 64 + 48];
            ull w7 = wb[kp * 64 + 56];
            ull x0 = x0p[kp];
            ull x1 = x0p[kp + 16 * XROWU];
            ull x2 = x0p[kp + 32 * XROWU];
            ull x3 = x0p[kp + 48 * XROWU];
            acc[0][0] = fma2(w0, x0, acc[0][0]);
            acc[0][1] = fma2(w1, x0, acc[0][1]);
            acc[0][2] = fma2(w2, x0, acc[0][2]);
            acc[0][3] = fma2(w3, x0, acc[0][3]);
            acc[0][4] = fma2(w4, x0, acc[0][4]);
            acc[0][5] = fma2(w5, x0, acc[0][5]);
            acc[0][6] = fma2(w6, x0, acc[0][6]);
            acc[0][7] = fma2(w7, x0, acc[0][7]);
            acc[1][0] = fma2(w0, x1, acc[1][0]);
            acc[1][1] = fma2(w1, x1, acc[1][1]);
            acc[1][2] = fma2(w2, x1, acc[1][2]);
            acc[1][3] = fma2(w3, x1, acc[1][3]);
            acc[1][4] = fma2(w4, x1, acc[1][4]);
            acc[1][5] = fma2(w5, x1, acc[1][5]);
            acc[1][6] = fma2(w6, x1, acc[1][6]);
            acc[1][7] = fma2(w7, x1, acc[1][7]);
            acc[2][0] = fma2(w0, x2, acc[2][0]);
            acc[2][1] = fma2(w1, x2, acc[2][1]);
            acc[2][2] = fma2(w2, x2, acc[2][2]);
            acc[2][3] = fma2(w3, x2, acc[2][3]);
            acc[2][4] = fma2(w4, x2, acc[2][4]);
            acc[2][5] = fma2(w5, x2, acc[2][5]);
            acc[2][6] = fma2(w6, x2, acc[2][6]);
            acc[2][7] = fma2(w7, x2, acc[2][7]);
            acc[3][0] = fma2(w0, x3, acc[3][0]);
            acc[3][1] = fma2(w1, x3, acc[3][1]);
            acc[3][2] = fma2(w2, x3, acc[3][2]);
            acc[3][3] = fma2(w3, x3, acc[3][3]);
            acc[3][4] = fma2(w4, x3, acc[3][4]);
            acc[3][5] = fma2(w5, x3, acc[3][5]);
            acc[3][6] = fma2(w6, x3, acc[3][6]);
            acc[3][7] = fma2(w7, x3, acc[3][7]);
        }
    }

    // ---- combine the two K-crews ----
    // Crew 1 writes reduced partials (lo+hi) into ITS OWN W staging region
    // (crew 0 never reads Wsm[1]); rows of REDROW=36 floats (144B, 16B-aligned).
    float* red = (float*)&Wsm[1][0][0];   // 128 rows x 36 floats = 18.4 KB < 24 KB
    if (ks == 1) {
#pragma unroll
        for (int j = 0; j < 4; j++) {
            float4 a, b4;
            float lo, hi;
            unpack2(acc[j][0], lo, hi); a.x = lo + hi;
            unpack2(acc[j][1], lo, hi); a.y = lo + hi;
            unpack2(acc[j][2], lo, hi); a.z = lo + hi;
            unpack2(acc[j][3], lo, hi); a.w = lo + hi;
            unpack2(acc[j][4], lo, hi); b4.x = lo + hi;
            unpack2(acc[j][5], lo, hi); b4.y = lo + hi;
            unpack2(acc[j][6], lo, hi); b4.z = lo + hi;
            unpack2(acc[j][7], lo, hi); b4.w = lo + hi;
            *(float4*)(red + t128 * REDROW + j * 8)     = a;
            *(float4*)(red + t128 * REDROW + j * 8 + 4) = b4;
        }
    }
    __syncthreads();

    if (ks == 0) {
        const int half = out_size >> 1;
        const int e0 = sub * 8;
        float bv[8];
#pragma unroll
        for (int p = 0; p < 8; p++) bv[p] = bias[e0 + p];

#pragma unroll
        for (int j = 0; j < 4; j++) {
            float4 ra = *(const float4*)(red + t128 * REDROW + j * 8);
            float4 rb = *(const float4*)(red + t128 * REDROW + j * 8 + 4);
            float other[8] = { ra.x, ra.y, ra.z, ra.w, rb.x, rb.y, rb.z, rb.w };

            float v0 = -3.4e38f, v1 = -3.4e38f;
            int   i0 = -1,       i1 = -1;
#pragma unroll
            for (int p = 0; p < 8; p++) {
                float lo, hi;
                unpack2(acc[j][p], lo, hi);
                float f = lo + hi + other[p] + bv[p];
                int e = e0 + p;
                if (f > v0)      { v1 = v0; i1 = i0; v0 = f; i0 = e; }
                else if (f > v1) { v1 = f;  i1 = e; }
            }
            // butterfly merge over the 8 sub-lanes owning this token
#pragma unroll
            for (int ofs = 1; ofs < 8; ofs <<= 1) {
                float u0 = __shfl_xor_sync(0xFFFFFFFFu, v0, ofs);
                float u1 = __shfl_xor_sync(0xFFFFFFFFu, v1, ofs);
                int   j0 = __shfl_xor_sync(0xFFFFFFFFu, i0, ofs);
                int   j1 = __shfl_xor_sync(0xFFFFFFFFu, i1, ofs);
                bool afirst = (v0 > u0) || (v0 == u0 && i0 < j0);
                float nv0, nv1; int ni0, ni1;
                if (afirst) {
                    nv0 = v0; ni0 = i0;
                    bool s = (u0 > v1) || (u0 == v1 && j0 < i1);
                    nv1 = s ? u0 : v1; ni1 = s ? j0 : i1;
                } else {
                    nv0 = u0; ni0 = j0;
                    bool s = (v0 > u1) || (v0 == u1 && i0 < j1);
                    nv1 = s ? v0 : u1; ni1 = s ? i0 : j1;
                }
                v0 = nv0; v1 = nv1; i0 = ni0; i1 = ni1;
            }
            if (sub == 0) {
                int tok = tokBase + tp + 16 * j;
                float e  = expf(v1 - v0);
                float s0 = 1.0f / (1.0f + e);
                float s1 = e * s0;
                out[tok * 2 + 0] = (float)i0;
                out[tok * 2 + 1] = (float)i1;
                out[half + tok * 2 + 0] = s0;
                out[half + tok * 2 + 1] = s1;
            }
        }
    }
}

extern "C" void kernel_launch(void* const* d_in, const int* in_sizes, int n_in,
                              void* d_out, int out_size) {
    const float* inp  = (const float*)d_in[0];   // [16384, 2048]
    const float* W    = (const float*)d_in[1];   // [64, 2048]
    const float* bias = (const float*)d_in[2];   // [64]
    float* out = (float*)d_out;

    prep_W<<<(DIM * NEXP + 255) / 256, 256>>>(W);
    gate_kernel<<<NTOK / TOKB, THREADS>>>(inp, bias, out, out_size);
}

// round 9
// speedup vs baseline: 3.1655x; 2.5280x over previous
#include <cuda_runtime.h>
#include <cuda_fp16.h>

#define NTOK 16384
#define NEXP 64
#define DIM  2048
#define KCH  64                    // original k per chunk
#define NCHUNK (DIM / KCH)         // 32
#define TOKB 64
#define THREADS 256
#define ROWH 72                    // padded row: 72 halfs = 144B (16B-aligned, ldmatrix conflict-free)
#define SPLITB (64 * ROWH * 2)     // 9216 B per split tile (64 rows x 144B)
#define BUFB   (2 * SPLITB)        // 18432 B per buffer (2 splits)
#define WCHUNKB BUFB               // prep W chunk block size
// dynamic smem layout
#define XOFF 0
#define WOFF (2 * BUFB)            // 36864
#define BOFF (4 * BUFB)            // 73728
#define SMTOT (BOFF + 256)         // 73984
#define INV256 0.00390625f

typedef unsigned long long ull;

// W pre-scaled x256, fp16 2-split, padded layout: gW[c][split][exp][ROWH]
__device__ __align__(16) __half gW[NCHUNK * 2 * NEXP * ROWH];

// ---------- helpers ----------
__device__ __forceinline__ unsigned smem_u32(const void* p) {
    unsigned a;
    asm("{ .reg .u64 t; cvta.to.shared.u64 t, %1; cvt.u32.u64 %0, t; }" : "=r"(a) : "l"(p));
    return a;
}
__device__ __forceinline__ void cpasync16(unsigned s, const void* g) {
    asm volatile("cp.async.cg.shared.global [%0], [%1], 16;" :: "r"(s), "l"(g));
}
__device__ __forceinline__ void ldm4(unsigned* r, unsigned addr) {
    asm volatile("ldmatrix.sync.aligned.m8n8.x4.shared.b16 {%0,%1,%2,%3}, [%4];"
                 : "=r"(r[0]), "=r"(r[1]), "=r"(r[2]), "=r"(r[3]) : "r"(addr));
}
__device__ __forceinline__ void mma16816(float* d, const unsigned* a, const unsigned* b) {
    asm volatile("mma.sync.aligned.m16n8k16.row.col.f32.f16.f16.f32 "
                 "{%0,%1,%2,%3}, {%4,%5,%6,%7}, {%8,%9}, {%0,%1,%2,%3};"
                 : "+f"(d[0]), "+f"(d[1]), "+f"(d[2]), "+f"(d[3])
                 : "r"(a[0]), "r"(a[1]), "r"(a[2]), "r"(a[3]), "r"(b[0]), "r"(b[1]));
}

// ---------- kernel 1: scale + split + pad W ----------
__global__ void prep_W(const float* __restrict__ W) {
    int i = blockIdx.x * blockDim.x + threadIdx.x;
    if (i >= NEXP * DIM) return;
    int e = i >> 11, k = i & (DIM - 1);
    int c = k >> 6, kin = k & 63;
    float x = W[i] * 256.0f;
    __half h = __float2half_rn(x);
    float r = x - __half2float(h);
    __half m = __float2half_rn(r);
    gW[((c * 2 + 0) * NEXP + e) * ROWH + kin] = h;
    gW[((c * 2 + 1) * NEXP + e) * ROWH + kin] = m;
}

// ---------- kernel 2: fp16 2-split HMMA GEMM + bias + top-2 + softmax ----------
__global__ __launch_bounds__(THREADS, 2)
void gate_hmma(const float* __restrict__ inp,
               const float* __restrict__ bias,
               float* __restrict__ out,
               int out_size) {
    extern __shared__ __align__(16) char smem[];
    const unsigned SB = smem_u32(smem);
    const unsigned XD = SB + XOFF;
    const unsigned WD = SB + WOFF;
    float* bsm = (float*)(smem + BOFF);

    const int tid  = threadIdx.x;
    const int wid  = tid >> 5;
    const int lane = tid & 31;
    const int tg   = wid & 1;        // token group: tokens tg*32 .. tg*32+31
    const int kq   = wid >> 1;       // K quarter: k-slice kq*16 within each 64-k chunk
    const int tokBase = blockIdx.x * TOKB;

    if (tid < 64) bsm[tid] = bias[tid];

    // X staging geometry: thread -> (token, k-quarter-of-chunk)
    const int xTok = tid >> 2;
    const int xq   = tid & 3;

    // ldmatrix lane-constant offsets (bytes)
    const unsigned aConst = (unsigned)((tg * 32 + (lane & 15)) * 144 + kq * 32 + ((lane >> 4) << 4));
    const unsigned bConst = (unsigned)(((lane & 7) + ((lane >> 4) << 3)) * 144 + kq * 32 + (((lane >> 3) & 1) << 4));

    float d0[8][4], d1[8][4];
#pragma unroll
    for (int j = 0; j < 8; j++)
#pragma unroll
        for (int q = 0; q < 4; q++) { d0[j][q] = 0.f; d1[j][q] = 0.f; }

    // ---- stage chunk 0 ----
    {
        const char* ws = (const char*)gW;
        unsigned wd = WD;
#pragma unroll
        for (int j = 0; j < 5; j++) {
            int o = tid + j * 256;
            if (o < BUFB / 16) cpasync16(wd + o * 16, ws + o * 16);
        }
        asm volatile("cp.async.commit_group;");
        const float4* xs = (const float4*)(inp + (size_t)(tokBase + xTok) * DIM + xq * 16);
        float4 v0 = xs[0], v1 = xs[1], v2 = xs[2], v3 = xs[3];
        float xv[16] = {v0.x,v0.y,v0.z,v0.w, v1.x,v1.y,v1.z,v1.w,
                        v2.x,v2.y,v2.z,v2.w, v3.x,v3.y,v3.z,v3.w};
        unsigned hw[8], mw[8];
#pragma unroll
        for (int i = 0; i < 8; i++) {
            __half2 h2 = __floats2half2_rn(xv[2*i], xv[2*i+1]);
            float2 hf = __half22float2(h2);
            __half2 m2 = __floats2half2_rn(xv[2*i] - hf.x, xv[2*i+1] - hf.y);
            hw[i] = *(unsigned*)&h2;
            mw[i] = *(unsigned*)&m2;
        }
        char* xh = smem + XOFF + xTok * 144 + xq * 32;
        ((uint4*)xh)[0] = make_uint4(hw[0], hw[1], hw[2], hw[3]);
        ((uint4*)xh)[1] = make_uint4(hw[4], hw[5], hw[6], hw[7]);
        char* xm = xh + SPLITB;
        ((uint4*)xm)[0] = make_uint4(mw[0], mw[1], mw[2], mw[3]);
        ((uint4*)xm)[1] = make_uint4(mw[4], mw[5], mw[6], mw[7]);
        asm volatile("cp.async.wait_group 0;");
    }
    __syncthreads();

    for (int c = 0; c < NCHUNK; c++) {
        const int b = c & 1;
        const bool has = (c + 1 < NCHUNK);
        float4 v0, v1, v2, v3;
        if (has) {
            const char* ws = (const char*)gW + (size_t)(c + 1) * WCHUNKB;
            unsigned wd = WD + (b ^ 1) * BUFB;
#pragma unroll
            for (int j = 0; j < 5; j++) {
                int o = tid + j * 256;
                if (o < BUFB / 16) cpasync16(wd + o * 16, ws + o * 16);
            }
            asm volatile("cp.async.commit_group;");
            const float4* xs = (const float4*)(inp + (size_t)(tokBase + xTok) * DIM + (c + 1) * KCH + xq * 16);
            v0 = xs[0]; v1 = xs[1]; v2 = xs[2]; v3 = xs[3];
        }

        // ---- compute chunk c (this warp's k16 slice, 3 split-terms) ----
        {
            const unsigned xA = XD + b * BUFB + aConst;
            const unsigned wA = WD + b * BUFB + bConst;
            unsigned ah0[4], ah1[4], am0[4], am1[4];
            ldm4(ah0, xA);
            ldm4(ah1, xA + 2304);
            ldm4(am0, xA + SPLITB);
            ldm4(am1, xA + SPLITB + 2304);
#pragma unroll
            for (int g = 0; g < 4; g++) {
                unsigned bh[4], bm[4];
                ldm4(bh, wA + g * 2304);
                ldm4(bm, wA + SPLITB + g * 2304);
                mma16816(d0[2*g],   ah0, bh);     mma16816(d0[2*g+1], ah0, bh + 2);
                mma16816(d1[2*g],   ah1, bh);     mma16816(d1[2*g+1], ah1, bh + 2);
                mma16816(d0[2*g],   ah0, bm);     mma16816(d0[2*g+1], ah0, bm + 2);
                mma16816(d1[2*g],   ah1, bm);     mma16816(d1[2*g+1], ah1, bm + 2);
                mma16816(d0[2*g],   am0, bh);     mma16816(d0[2*g+1], am0, bh + 2);
                mma16816(d1[2*g],   am1, bh);     mma16816(d1[2*g+1], am1, bh + 2);
            }
        }

        if (has) {
            float xv[16] = {v0.x,v0.y,v0.z,v0.w, v1.x,v1.y,v1.z,v1.w,
                            v2.x,v2.y,v2.z,v2.w, v3.x,v3.y,v3.z,v3.w};
            unsigned hw[8], mw[8];
#pragma unroll
            for (int i = 0; i < 8; i++) {
                __half2 h2 = __floats2half2_rn(xv[2*i], xv[2*i+1]);
                float2 hf = __half22float2(h2);
                __half2 m2 = __floats2half2_rn(xv[2*i] - hf.x, xv[2*i+1] - hf.y);
                hw[i] = *(unsigned*)&h2;
                mw[i] = *(unsigned*)&m2;
            }
            char* xh = smem + XOFF + (b ^ 1) * BUFB + xTok * 144 + xq * 32;
            ((uint4*)xh)[0] = make_uint4(hw[0], hw[1], hw[2], hw[3]);
            ((uint4*)xh)[1] = make_uint4(hw[4], hw[5], hw[6], hw[7]);
            char* xm = xh + SPLITB;
            ((uint4*)xm)[0] = make_uint4(mw[0], mw[1], mw[2], mw[3]);
            ((uint4*)xm)[1] = make_uint4(mw[4], mw[5], mw[6], mw[7]);
        }
        asm volatile("cp.async.wait_group 0;");
        __syncthreads();
    }

    // ---- reduce across the 4 K-quarter crews (scratch = reuse staging smem) ----
    float* scr = (float*)smem;   // rows of 68 floats (272B)
    __syncthreads();

    // round 1: kq 2,3 write; kq 0,1 add
    if (kq >= 2) {
        int row = (tg * 2 + (kq - 2)) * 32 + lane;
#pragma unroll
        for (int j = 0; j < 8; j++)
            *(float4*)(scr + row * 68 + j * 4) = make_float4(d0[j][0], d0[j][1], d0[j][2], d0[j][3]);
#pragma unroll
        for (int j = 0; j < 8; j++)
            *(float4*)(scr + row * 68 + 32 + j * 4) = make_float4(d1[j][0], d1[j][1], d1[j][2], d1[j][3]);
    }
    __syncthreads();
    if (kq < 2) {
        int row = (tg * 2 + kq) * 32 + lane;
#pragma unroll
        for (int j = 0; j < 8; j++) {
            float4 v = *(const float4*)(scr + row * 68 + j * 4);
            d0[j][0] += v.x; d0[j][1] += v.y; d0[j][2] += v.z; d0[j][3] += v.w;
        }
#pragma unroll
        for (int j = 0; j < 8; j++) {
            float4 v = *(const float4*)(scr + row * 68 + 32 + j * 4);
            d1[j][0] += v.x; d1[j][1] += v.y; d1[j][2] += v.z; d1[j][3] += v.w;
        }
    }
    __syncthreads();
    // round 2: kq 1 writes; kq 0 adds
    if (kq == 1) {
        int row = tg * 32 + lane;
#pragma unroll
        for (int j = 0; j < 8; j++)
            *(float4*)(scr + row * 68 + j * 4) = make_float4(d0[j][0], d0[j][1], d0[j][2], d0[j][3]);
#pragma unroll
        for (int j = 0; j < 8; j++)
            *(float4*)(scr + row * 68 + 32 + j * 4) = make_float4(d1[j][0], d1[j][1], d1[j][2], d1[j][3]);
    }
    __syncthreads();

    if (kq == 0) {
        int row = tg * 32 + lane;
#pragma unroll
        for (int j = 0; j < 8; j++) {
            float4 v = *(const float4*)(scr + row * 68 + j * 4);
            d0[j][0] += v.x; d0[j][1] += v.y; d0[j][2] += v.z; d0[j][3] += v.w;
        }
#pragma unroll
        for (int j = 0; j < 8; j++) {
            float4 v = *(const float4*)(scr + row * 68 + 32 + j * 4);
            d1[j][0] += v.x; d1[j][1] += v.y; d1[j][2] += v.z; d1[j][3] += v.w;
        }

        // ---- epilogue: unscale, +bias, top-2 over 64, softmax ----
        const int half = out_size >> 1;
#pragma unroll
        for (int mt = 0; mt < 2; mt++) {
#pragma unroll
            for (int rh = 0; rh < 2; rh++) {
                float v0 = -3.4e38f, v1 = -3.4e38f;
                int   i0 = -1,       i1 = -1;
#pragma unroll
                for (int j = 0; j < 8; j++) {
#pragma unroll
                    for (int v = 0; v < 2; v++) {
                        int e = j * 8 + (lane & 3) * 2 + v;
                        float dv = (mt == 0) ? d0[j][rh * 2 + v] : d1[j][rh * 2 + v];
                        float f = dv * INV256 + bsm[e];
                        if (f > v0)      { v1 = v0; i1 = i0; v0 = f; i0 = e; }
                        else if (f > v1) { v1 = f;  i1 = e; }
                    }
                }
                // merge across the quad owning this row
#pragma unroll
                for (int ofs = 1; ofs < 4; ofs <<= 1) {
                    float u0 = __shfl_xor_sync(0xFFFFFFFFu, v0, ofs);
                    float u1 = __shfl_xor_sync(0xFFFFFFFFu, v1, ofs);
                    int   j0 = __shfl_xor_sync(0xFFFFFFFFu, i0, ofs);
                    int   j1 = __shfl_xor_sync(0xFFFFFFFFu, i1, ofs);
                    bool afirst = (v0 > u0) || (v0 == u0 && i0 < j0);
                    float nv0, nv1; int ni0, ni1;
                    if (afirst) {
                        nv0 = v0; ni0 = i0;
                        bool s = (u0 > v1) || (u0 == v1 && j0 < i1);
                        nv1 = s ? u0 : v1; ni1 = s ? j0 : i1;
                    } else {
                        nv0 = u0; ni0 = j0;
                        bool s = (v0 > u1) || (v0 == u1 && i0 < j1);
                        nv1 = s ? v0 : u1; ni1 = s ? i0 : j1;
                    }
                    v0 = nv0; v1 = nv1; i0 = ni0; i1 = ni1;
                }
                if ((lane & 3) == 0) {
                    int tok = tokBase + tg * 32 + mt * 16 + rh * 8 + (lane >> 2);
                    float ex = expf(v1 - v0);
                    float s0 = 1.0f / (1.0f + ex);
                    float s1 = ex * s0;
                    out[tok * 2 + 0] = (float)i0;
                    out[tok * 2 + 1] = (float)i1;
                    out[half + tok * 2 + 0] = s0;
                    out[half + tok * 2 + 1] = s1;
                }
            }
        }
    }
}

extern "C" void kernel_launch(void* const* d_in, const int* in_sizes, int n_in,
                              void* d_out, int out_size) {
    const float* inp  = (const float*)d_in[0];   // [16384, 2048]
    const float* W    = (const float*)d_in[1];   // [64, 2048]
    const float* bias = (const float*)d_in[2];   // [64]
    float* out = (float*)d_out;

    cudaFuncSetAttribute(gate_hmma, cudaFuncAttributeMaxDynamicSharedMemorySize, SMTOT);
    prep_W<<<(NEXP * DIM + 255) / 256, 256>>>(W);
    gate_hmma<<<NTOK / TOKB, THREADS, SMTOT>>>(inp, bias, out, out_size);
}